// round 14
// baseline (speedup 1.0000x reference)
#include <cuda_runtime.h>
#include <cuda_bf16.h>
#include <cstdint>
#include <math.h>

#define NN 131072
#define EE 1000000

// proj/out mma smem layout (u32 units), 256-row block
#define U2_AH   0        // 256 * 36
#define U2_AL   9216
#define U2_BH   18432    // 64 * 36
#define U2_BL   20736
#define U2_BIAS 23040    // 320 floats
#define SMEM_MMA2 ((23040 + 320) * 4)

typedef unsigned long long u64;

// ---------------- static device scratch ----------------
__device__ __align__(128) float gXA[NN * 64];
__device__ __align__(128) float gXB[NN * 64];
__device__ __align__(128) float gBufA[(size_t)NN * 320]; // [q | rel0 kv | rel2 kv]
__device__ __align__(128) float gBufB[(size_t)NN * 192]; // [q | rel1 kv]
__device__ __align__(128) float gAggA[NN * 64];
__device__ __align__(128) float gAggB[NN * 64];
__device__ __align__(128) float gWfA[64 * 320];
__device__ float gBfA[320];
__device__ __align__(128) float gWfB[64 * 192];
__device__ float gBfB[192];
// packed W (bf16 hi/lo pairs), B-frag order: [col][kpair]
__device__ __align__(128) uint32_t gWAh[320 * 32];
__device__ __align__(128) uint32_t gWAl[320 * 32];
__device__ __align__(128) uint32_t gWBh[192 * 32];
__device__ __align__(128) uint32_t gWBl[192 * 32];
// packed Wa for output projection: [typ][col*32 + kp], 64 cols x 32 kpairs
__device__ __align__(128) uint32_t gWOh[2][64 * 32];
__device__ __align__(128) uint32_t gWOl[2][64 * 32];
__device__ int   gRowptr[3][NN + 1];
__device__ int   gCur3[3][NN];
__device__ int   gBlkSum[3][128];
__device__ int   gCsr[3][EE];

// ---------------- bf16 split helper ----------------
__device__ __forceinline__ uint32_t pack_bf16_hi(float a, float b, uint32_t& lo_out) {
    __nv_bfloat16 ha = __float2bfloat16_rn(a);
    __nv_bfloat16 hb = __float2bfloat16_rn(b);
    __nv_bfloat16 la = __float2bfloat16_rn(a - __bfloat162float(ha));
    __nv_bfloat16 lb = __float2bfloat16_rn(b - __bfloat162float(hb));
    unsigned short uha = *(unsigned short*)&ha, uhb = *(unsigned short*)&hb;
    unsigned short ula = *(unsigned short*)&la, ulb = *(unsigned short*)&lb;
    lo_out = (uint32_t)ula | ((uint32_t)ulb << 16);
    return (uint32_t)uha | ((uint32_t)uhb << 16);
}

// m16n8k16 bf16 MMA, f32 accum
__device__ __forceinline__ void mma16816(float* c, const uint32_t* a, const uint32_t* b) {
    asm volatile(
        "mma.sync.aligned.m16n8k16.row.col.f32.bf16.bf16.f32 "
        "{%0,%1,%2,%3}, {%4,%5,%6,%7}, {%8,%9}, {%0,%1,%2,%3};"
        : "+f"(c[0]), "+f"(c[1]), "+f"(c[2]), "+f"(c[3])
        : "r"(a[0]), "r"(a[1]), "r"(a[2]), "r"(a[3]), "r"(b[0]), "r"(b[1]));
}

// ---------------- misc ----------------
__device__ __forceinline__ float warpsum(float p) {
    p += __shfl_xor_sync(0xffffffffu, p, 16);
    p += __shfl_xor_sync(0xffffffffu, p, 8);
    p += __shfl_xor_sync(0xffffffffu, p, 4);
    p += __shfl_xor_sync(0xffffffffu, p, 2);
    p += __shfl_xor_sync(0xffffffffu, p, 1);
    return p;
}
__device__ __forceinline__ void warpsum2(float& a, float& b) {
#pragma unroll
    for (int o = 16; o; o >>= 1) {
        a += __shfl_xor_sync(0xffffffffu, a, o);
        b += __shfl_xor_sync(0xffffffffu, b, o);
    }
}
__device__ __forceinline__ int wscan_incl(int x, int lane) {
#pragma unroll
    for (int o = 1; o < 32; o <<= 1) {
        int y = __shfl_up_sync(0xffffffffu, x, o);
        if (lane >= o) x += y;
    }
    return x;
}
__device__ __forceinline__ float gelu_f(float v) {
    return 0.5f * v * (1.0f + erff(v * 0.7071067811865476f));
}
__device__ __forceinline__ void online_upd(float sc, float vz, float vw,
                                           float& mx, float& den, float& s0, float& s1) {
    if (sc > mx) {
        float f = __expf(mx - sc);
        den = den * f + 1.f;
        s0  = s0 * f + vz;
        s1  = s1 * f + vw;
        mx = sc;
    } else {
        float e = __expf(sc - mx);
        den += e;
        s0  += e * vz;
        s1  += e * vw;
    }
}

// ---------------- input staging ----------------
__global__ void k_copyin(const float* __restrict__ xA, const float* __restrict__ xB) {
    int i = blockIdx.x * blockDim.x + threadIdx.x;
    gXA[i] = xA[i];
    gXB[i] = xB[i];
}

// ---------------- CSR build ----------------
__global__ void k_zero_deg() {
    int rel = blockIdx.y;
    int i = blockIdx.x * blockDim.x + threadIdx.x;
    if (i < NN) gRowptr[rel][i] = 0;
}
__global__ void k_hist(const int* __restrict__ e0, const int* __restrict__ e1,
                       const int* __restrict__ e2) {
    int rel = blockIdx.y;
    const int* ei = rel == 0 ? e0 : rel == 1 ? e1 : e2;
    int e = blockIdx.x * blockDim.x + threadIdx.x;
    if (e < EE) atomicAdd(&gRowptr[rel][ei[EE + e]], 1);
}
__global__ void k_blocksum() {
    int rel = blockIdx.y;
    int i = blockIdx.x * 1024 + threadIdx.x;
    int lane = threadIdx.x & 31, wid = threadIdx.x >> 5;
    int s = gRowptr[rel][i];
#pragma unroll
    for (int o = 16; o; o >>= 1) s += __shfl_xor_sync(0xffffffffu, s, o);
    __shared__ int sh[32];
    if (lane == 0) sh[wid] = s;
    __syncthreads();
    if (wid == 0) {
        int t = sh[lane];
#pragma unroll
        for (int o = 16; o; o >>= 1) t += __shfl_xor_sync(0xffffffffu, t, o);
        if (lane == 0) gBlkSum[rel][blockIdx.x] = t;
    }
}
__global__ void k_scanblk() {
    int tid = threadIdx.x, lane = tid & 31, wid = tid >> 5;
    __shared__ int ws[4];
    for (int rel = 0; rel < 3; rel++) {
        int v = gBlkSum[rel][tid];
        int x = wscan_incl(v, lane);
        __syncthreads();
        if (lane == 31) ws[wid] = x;
        __syncthreads();
        int add = 0;
#pragma unroll
        for (int w = 0; w < 4; w++) add += (w < wid) ? ws[w] : 0;
        gBlkSum[rel][tid] = x + add - v;
        __syncthreads();
    }
}
__global__ void k_scanlocal() {
    int rel = blockIdx.y;
    int idx = blockIdx.x * 1024 + threadIdx.x;
    int lane = threadIdx.x & 31, wid = threadIdx.x >> 5;
    int v = gRowptr[rel][idx];
    int x = wscan_incl(v, lane);
    __shared__ int ws[32];
    if (lane == 31) ws[wid] = x;
    __syncthreads();
    if (wid == 0) ws[lane] = wscan_incl(ws[lane], lane);
    __syncthreads();
    int incl = x + (wid ? ws[wid - 1] : 0);
    int excl = incl - v + gBlkSum[rel][blockIdx.x];
    gRowptr[rel][idx] = excl;
    gCur3[rel][idx] = excl;
    if (idx == NN - 1) gRowptr[rel][NN] = excl + v;
}
__global__ void k_scatter(const int* __restrict__ e0, const int* __restrict__ e1,
                          const int* __restrict__ e2) {
    int rel = blockIdx.y;
    const int* ei = rel == 0 ? e0 : rel == 1 ? e1 : e2;
    int e = blockIdx.x * blockDim.x + threadIdx.x;
    if (e >= EE) return;
    int dst = ei[EE + e];
    int pos = atomicAdd(&gCur3[rel][dst], 1);
    gCsr[rel][pos] = ei[e];
}

// ---------------- per-layer fused weight build ----------------
__device__ float fuse_elem(int typ, int i, int j, int l,
                           const float* __restrict__ Wk, const float* __restrict__ bk,
                           const float* __restrict__ Wq, const float* __restrict__ bq,
                           const float* __restrict__ Wv, const float* __restrict__ bv,
                           const float* __restrict__ Ar, const float* __restrict__ Mr) {
    if (j < 64) {
        if (i >= 0) return Wq[(size_t)(l * 2 + typ) * 4096 + i * 64 + j];
        return bq[(l * 2 + typ) * 64 + j];
    }
    int t = j - 64, rel;
    if (typ == 0) { rel = (t >> 7) ? 2 : 0; t &= 127; }
    else rel = 1;
    int lane = t >> 2, c = t & 3;
    int isK = (c < 2);
    int dcol = 2 * lane + (c & 1);
    const float* R = (isK ? Ar : Mr) + (size_t)(l * 3 + rel) * 4096;
    float s = 0.f;
    if (i >= 0) {
        const float* w = (isK ? Wk : Wv) + (size_t)(l * 2 + typ) * 4096 + i * 64;
#pragma unroll
        for (int d = 0; d < 64; d++) s += w[d] * R[d * 64 + dcol];
    } else {
        const float* b = (isK ? bk : bv) + (l * 2 + typ) * 64;
#pragma unroll
        for (int d = 0; d < 64; d++) s += b[d] * R[d * 64 + dcol];
    }
    return s;
}
__global__ void k_fuse(const float* __restrict__ Wk, const float* __restrict__ bk,
                       const float* __restrict__ Wq, const float* __restrict__ bq,
                       const float* __restrict__ Wv, const float* __restrict__ bv,
                       const float* __restrict__ Ar, const float* __restrict__ Mr, int l) {
    int id = blockIdx.x * blockDim.x + threadIdx.x;
    if (id < 20480) {
        int i = id / 320, j = id % 320;
        gWfA[id] = fuse_elem(0, i, j, l, Wk, bk, Wq, bq, Wv, bv, Ar, Mr);
    } else if (id < 32768) {
        int idx = id - 20480;
        int i = idx / 192, j = idx % 192;
        gWfB[idx] = fuse_elem(1, i, j, l, Wk, bk, Wq, bq, Wv, bv, Ar, Mr);
    } else if (id < 33088) {
        int j = id - 32768;
        gBfA[j] = fuse_elem(0, -1, j, l, Wk, bk, Wq, bq, Wv, bv, Ar, Mr);
    } else if (id < 33280) {
        int j = id - 33088;
        gBfB[j] = fuse_elem(1, -1, j, l, Wk, bk, Wq, bq, Wv, bv, Ar, Mr);
    }
}

// ---------------- pack W once per layer into B-frag order ------------------
__global__ void k_packW() {
    int id = blockIdx.x * blockDim.x + threadIdx.x;
    if (id < 320 * 32) {
        int col = id >> 5, kp = id & 31;
        uint32_t lo, hi = pack_bf16_hi(gWfA[(2 * kp) * 320 + col],
                                       gWfA[(2 * kp + 1) * 320 + col], lo);
        gWAh[id] = hi;
        gWAl[id] = lo;
    } else if (id < 320 * 32 + 192 * 32) {
        int idx = id - 320 * 32;
        int col = idx >> 5, kp = idx & 31;
        uint32_t lo, hi = pack_bf16_hi(gWfB[(2 * kp) * 192 + col],
                                       gWfB[(2 * kp + 1) * 192 + col], lo);
        gWBh[idx] = hi;
        gWBl[idx] = lo;
    }
}

// pack Wa[l][typ] (64x64) into B-frag order: 2 typ x 2048 entries = 4096 threads
__global__ void k_packWa(const float* __restrict__ Wa, int l) {
    int id = blockIdx.x * blockDim.x + threadIdx.x;   // 4096 total
    int typ = id >> 11;                               // 0..1
    int idx = id & 2047;                              // 0..2047
    int col = idx >> 5, kp = idx & 31;                // col 0..63, kp 0..31
    const float* w = Wa + (size_t)(l * 2 + typ) * 4096;
    uint32_t lo, hi = pack_bf16_hi(w[(2 * kp) * 64 + col],
                                   w[(2 * kp + 1) * 64 + col], lo);
    gWOh[typ][idx] = hi;
    gWOl[typ][idx] = lo;
}

// ---------------- HMMA projection: 256 rows/block, loop over col groups ----
__global__ void __launch_bounds__(256, 2) k_proj_mma(int typ) {
    extern __shared__ uint32_t su[];
    const float* X   = typ ? gXB  : gXA;
    const uint32_t* WH = typ ? gWBh : gWAh;
    const uint32_t* WL = typ ? gWBl : gWAl;
    const float* Bf  = typ ? gBfB : gBfA;
    float*       Out = typ ? gBufB : gBufA;
    const int OC = typ ? 192 : 320;
    const int NCG = typ ? 3 : 5;

    uint32_t* AH = su + U2_AH;
    uint32_t* AL = su + U2_AL;
    uint32_t* BH = su + U2_BH;
    uint32_t* BL = su + U2_BL;
    float*    Bs = (float*)(su + U2_BIAS);

    int tid = threadIdx.x;
    size_t row0 = (size_t)blockIdx.x * 256;

    {
        const float4* xr = (const float4*)(X + (row0 + tid) * 64);
        int rb = tid * 36;
#pragma unroll
        for (int j = 0; j < 16; j++) {
            float4 v = xr[j];
            uint32_t lo0, lo1;
            uint32_t hi0 = pack_bf16_hi(v.x, v.y, lo0);
            uint32_t hi1 = pack_bf16_hi(v.z, v.w, lo1);
            AH[rb + 2 * j]     = hi0;
            AH[rb + 2 * j + 1] = hi1;
            AL[rb + 2 * j]     = lo0;
            AL[rb + 2 * j + 1] = lo1;
        }
    }
    for (int i = tid; i < OC; i += 256) Bs[i] = Bf[i];

    int w = tid >> 5, lid = tid & 31, g = lid >> 2, tig = lid & 3;
    int mo = w * 32;

    for (int cg = 0; cg < NCG; cg++) {
        int col0 = cg * 64;
        __syncthreads();
        for (int i = tid; i < 2048; i += 256) {
            int n = i >> 5, kp = i & 31;
            BH[n * 36 + kp] = WH[(size_t)(col0 + n) * 32 + kp];
            BL[n * 36 + kp] = WL[(size_t)(col0 + n) * 32 + kp];
        }
        __syncthreads();

        float c[2][8][4];
#pragma unroll
        for (int nt = 0; nt < 8; nt++) {
            float b0 = Bs[col0 + nt * 8 + tig * 2];
            float b1 = Bs[col0 + nt * 8 + tig * 2 + 1];
#pragma unroll
            for (int mt = 0; mt < 2; mt++) {
                c[mt][nt][0] = b0; c[mt][nt][1] = b1;
                c[mt][nt][2] = b0; c[mt][nt][3] = b1;
            }
        }

#pragma unroll
        for (int s = 0; s < 3; s++) {
            const uint32_t* Aa = (s < 2) ? AH : AL;
            const uint32_t* Ba = (s == 1) ? BL : BH;
#pragma unroll
            for (int ks = 0; ks < 4; ks++) {
                int ab = (mo + g) * 36 + ks * 8 + tig;
                uint32_t a[2][4];
                a[0][0] = Aa[ab];        a[0][2] = Aa[ab + 4];
                a[0][1] = Aa[ab + 288];  a[0][3] = Aa[ab + 292];
                a[1][0] = Aa[ab + 576];  a[1][2] = Aa[ab + 580];
                a[1][1] = Aa[ab + 864];  a[1][3] = Aa[ab + 868];
                int bb = g * 36 + ks * 8 + tig;
                uint32_t b[8][2];
#pragma unroll
                for (int nt = 0; nt < 8; nt++) {
                    b[nt][0] = Ba[bb + nt * 288];
                    b[nt][1] = Ba[bb + nt * 288 + 4];
                }
#pragma unroll
                for (int mt = 0; mt < 2; mt++)
#pragma unroll
                    for (int nt = 0; nt < 8; nt++)
                        mma16816(c[mt][nt], a[mt], b[nt]);
            }
        }

#pragma unroll
        for (int mt = 0; mt < 2; mt++) {
            size_t ra = row0 + mo + mt * 16 + g;
#pragma unroll
            for (int nt = 0; nt < 8; nt++) {
                float* p = Out + ra * OC + col0 + nt * 8 + tig * 2;
                *(float2*)p = make_float2(c[mt][nt][0], c[mt][nt][1]);
                *(float2*)(p + 8 * (size_t)OC) = make_float2(c[mt][nt][2], c[mt][nt][3]);
            }
        }
    }
}

// ---------------- HMMA output projection: gelu in pack, skip in epilogue ---
__global__ void __launch_bounds__(256, 2) k_out_mma(int typ, const float* __restrict__ ba,
                                                    const float* __restrict__ skip, int l) {
    extern __shared__ uint32_t su[];
    const float* agg = typ ? gAggB : gAggA;
    float* X = typ ? gXB : gXA;

    uint32_t* AH = su + U2_AH;
    uint32_t* AL = su + U2_AL;
    uint32_t* BH = su + U2_BH;
    uint32_t* BL = su + U2_BL;
    float*    Bs = (float*)(su + U2_BIAS);

    int tid = threadIdx.x;
    size_t row0 = (size_t)blockIdx.x * 256;

    // A pack with gelu fused
    {
        const float4* xr = (const float4*)(agg + (row0 + tid) * 64);
        int rb = tid * 36;
#pragma unroll
        for (int j = 0; j < 16; j++) {
            float4 v = xr[j];
            float g0 = gelu_f(v.x), g1 = gelu_f(v.y), g2 = gelu_f(v.z), g3 = gelu_f(v.w);
            uint32_t lo0, lo1;
            uint32_t hi0 = pack_bf16_hi(g0, g1, lo0);
            uint32_t hi1 = pack_bf16_hi(g2, g3, lo1);
            AH[rb + 2 * j]     = hi0;
            AH[rb + 2 * j + 1] = hi1;
            AL[rb + 2 * j]     = lo0;
            AL[rb + 2 * j + 1] = lo1;
        }
    }
    // packed B tile (coalesced)
    for (int i = tid; i < 2048; i += 256) {
        BH[(i >> 5) * 36 + (i & 31)] = gWOh[typ][i];
        BL[(i >> 5) * 36 + (i & 31)] = gWOl[typ][i];
    }
    if (tid < 64) Bs[tid] = ba[(l * 2 + typ) * 64 + tid];
    __syncthreads();

    int w = tid >> 5, lid = tid & 31, g = lid >> 2, tig = lid & 3;
    int mo = w * 32;

    float c[2][8][4];
#pragma unroll
    for (int nt = 0; nt < 8; nt++) {
        float b0 = Bs[nt * 8 + tig * 2];
        float b1 = Bs[nt * 8 + tig * 2 + 1];
#pragma unroll
        for (int mt = 0; mt < 2; mt++) {
            c[mt][nt][0] = b0; c[mt][nt][1] = b1;
            c[mt][nt][2] = b0; c[mt][nt][3] = b1;
        }
    }

#pragma unroll
    for (int s = 0; s < 3; s++) {
        const uint32_t* Aa = (s < 2) ? AH : AL;
        const uint32_t* Ba = (s == 1) ? BL : BH;
#pragma unroll
        for (int ks = 0; ks < 4; ks++) {
            int ab = (mo + g) * 36 + ks * 8 + tig;
            uint32_t a[2][4];
            a[0][0] = Aa[ab];        a[0][2] = Aa[ab + 4];
            a[0][1] = Aa[ab + 288];  a[0][3] = Aa[ab + 292];
            a[1][0] = Aa[ab + 576];  a[1][2] = Aa[ab + 580];
            a[1][1] = Aa[ab + 864];  a[1][3] = Aa[ab + 868];
            int bb = g * 36 + ks * 8 + tig;
            uint32_t b[8][2];
#pragma unroll
            for (int nt = 0; nt < 8; nt++) {
                b[nt][0] = Ba[bb + nt * 288];
                b[nt][1] = Ba[bb + nt * 288 + 4];
            }
#pragma unroll
            for (int mt = 0; mt < 2; mt++)
#pragma unroll
                for (int nt = 0; nt < 8; nt++)
                    mma16816(c[mt][nt], a[mt], b[nt]);
        }
    }

    float sg = 1.0f / (1.0f + __expf(-skip[l * 2 + typ]));
    float omg = 1.0f - sg;

#pragma unroll
    for (int mt = 0; mt < 2; mt++) {
        size_t ra = row0 + mo + mt * 16 + g;
#pragma unroll
        for (int nt = 0; nt < 8; nt++) {
            float* p = X + ra * 64 + nt * 8 + tig * 2;
            float2 x0 = *(float2*)p;
            float2 x1 = *(float2*)(p + 8 * 64);
            *(float2*)p = make_float2(sg * c[mt][nt][0] + omg * x0.x,
                                      sg * c[mt][nt][1] + omg * x0.y);
            *(float2*)(p + 8 * 64) = make_float2(sg * c[mt][nt][2] + omg * x1.x,
                                                 sg * c[mt][nt][3] + omg * x1.y);
        }
    }
}

// ---------------- edge attention: TWO-STREAM online softmax ----------------
template <int REL, int ACCUM>
__global__ void k_edge(const float* __restrict__ p_rel, int l) {
    int t = blockIdx.x * blockDim.x + threadIdx.x;
    int gw = t >> 5, lane = t & 31;
    if (gw >= NN) return;

    const float* Q;   int qs;
    const float* Src; int ss, off;
    float* Agg;
    if (REL == 0) { Q = gBufB; qs = 192; Src = gBufA; ss = 320; off = 64;  Agg = gAggB; }
    else if (REL == 1) { Q = gBufA; qs = 320; Src = gBufB; ss = 192; off = 64;  Agg = gAggA; }
    else { Q = gBufA; qs = 320; Src = gBufA; ss = 320; off = 192; Agg = gAggA; }

    float scl = p_rel[l * 3 + REL] * 0.125f;
    float2 q = *(const float2*)(Q + (size_t)gw * qs + 2 * lane);

    const int* __restrict__ rowptr = gRowptr[REL];
    const int* __restrict__ csr = gCsr[REL];
    int beg = rowptr[gw], end = rowptr[gw + 1];

    float mxA = -3.0e38f, denA = 0.f, s0A = 0.f, s1A = 0.f;
    float mxB = -3.0e38f, denB = 0.f, s0B = 0.f, s1B = 0.f;

    int j = beg;
    for (; j + 2 <= end; j += 2) {
        int sA = __ldg(&csr[j]);
        int sB = __ldg(&csr[j + 1]);
        float4 kvA = *(const float4*)(Src + (size_t)sA * ss + off + 4 * lane);
        float4 kvB = *(const float4*)(Src + (size_t)sB * ss + off + 4 * lane);
        float pA = fmaf(q.x, kvA.x, q.y * kvA.y);
        float pB = fmaf(q.x, kvB.x, q.y * kvB.y);
        warpsum2(pA, pB);
        online_upd(pA * scl, kvA.z, kvA.w, mxA, denA, s0A, s1A);
        online_upd(pB * scl, kvB.z, kvB.w, mxB, denB, s0B, s1B);
    }
    if (j < end) {
        int s = __ldg(&csr[j]);
        float4 kv = *(const float4*)(Src + (size_t)s * ss + off + 4 * lane);
        float sc = warpsum(fmaf(q.x, kv.x, q.y * kv.y)) * scl;
        online_upd(sc, kv.z, kv.w, mxA, denA, s0A, s1A);
    }

    float a0 = 0.f, a1 = 0.f;
    {
        float m = fmaxf(mxA, mxB);
        float fA = __expf(mxA - m), fB = __expf(mxB - m);
        float den = denA * fA + denB * fB;
        float s0 = s0A * fA + s0B * fB;
        float s1 = s1A * fA + s1B * fB;
        if (den > 0.f) {
            float inv = 1.0f / den;
            a0 = s0 * inv;
            a1 = s1 * inv;
        }
    }
    float2* ap = (float2*)(Agg + (size_t)gw * 64 + 2 * lane);
    if (ACCUM) {
        float2 old = *ap;
        *ap = make_float2(old.x + a0, old.y + a1);
    } else {
        *ap = make_float2(a0, a1);
    }
}

// ---------------- final pool + linear ----------------
__global__ void k_zero_out(float* out) { out[0] = 0.f; }

__global__ void k_final(const float* __restrict__ lw, const float* __restrict__ lb,
                        float* out) {
    float acc = 0.f;
    const int total = 2 * NN * 64;
    for (int i = blockIdx.x * blockDim.x + threadIdx.x; i < total;
         i += gridDim.x * blockDim.x) {
        float v = (i < NN * 64) ? gXA[i] : gXB[i - NN * 64];
        acc += v * lw[i & 63];
    }
    __shared__ float red[256];
    red[threadIdx.x] = acc;
    __syncthreads();
    for (int s = 128; s; s >>= 1) {
        if (threadIdx.x < s) red[threadIdx.x] += red[threadIdx.x + s];
        __syncthreads();
    }
    if (threadIdx.x == 0) {
        float v = red[0];
        if (blockIdx.x == 0) v += lb[0];
        atomicAdd(out, v);
    }
}

// ---------------- launch ----------------
extern "C" void kernel_launch(void* const* d_in, const int* in_sizes, int n_in,
                              void* d_out, int out_size) {
    const float* xA   = (const float*)d_in[0];
    const float* xB   = (const float*)d_in[1];
    const float* Wk   = (const float*)d_in[2];
    const float* bk   = (const float*)d_in[3];
    const float* Wq   = (const float*)d_in[4];
    const float* bq   = (const float*)d_in[5];
    const float* Wv   = (const float*)d_in[6];
    const float* bv   = (const float*)d_in[7];
    const float* Ar   = (const float*)d_in[8];
    const float* Mr   = (const float*)d_in[9];
    const float* pr   = (const float*)d_in[10];
    const float* Wa   = (const float*)d_in[11];
    const float* ba   = (const float*)d_in[12];
    const float* skip = (const float*)d_in[13];
    const float* lw   = (const float*)d_in[14];
    const float* lb   = (const float*)d_in[15];
    const int* e0 = (const int*)d_in[16];
    const int* e1 = (const int*)d_in[17];
    const int* e2 = (const int*)d_in[18];

    cudaFuncSetAttribute(k_proj_mma, cudaFuncAttributeMaxDynamicSharedMemorySize, SMEM_MMA2);
    cudaFuncSetAttribute(k_out_mma,  cudaFuncAttributeMaxDynamicSharedMemorySize, SMEM_MMA2);
    cudaFuncSetAttribute(k_proj_mma, cudaFuncAttributePreferredSharedMemoryCarveout, 100);
    cudaFuncSetAttribute(k_out_mma,  cudaFuncAttributePreferredSharedMemoryCarveout, 100);

    // Layer-0 GEMMs first so launch index 3 (ncu capture slot) is k_proj_mma(A).
    k_copyin<<<NN * 64 / 256, 256>>>(xA, xB);                      // 0
    k_fuse<<<130, 256>>>(Wk, bk, Wq, bq, Wv, bv, Ar, Mr, 0);       // 1
    k_packW<<<64, 256>>>();                                        // 2
    k_proj_mma<<<512, 256, SMEM_MMA2>>>(0);                        // 3 <- profiled
    k_proj_mma<<<512, 256, SMEM_MMA2>>>(1);                        // 4

    // CSR build
    k_zero_deg<<<dim3(NN / 256, 3), 256>>>();
    k_hist<<<dim3((EE + 255) / 256, 3), 256>>>(e0, e1, e2);
    k_blocksum<<<dim3(128, 3), 1024>>>();
    k_scanblk<<<1, 128>>>();
    k_scanlocal<<<dim3(128, 3), 1024>>>();
    k_scatter<<<dim3((EE + 255) / 256, 3), 256>>>(e0, e1, e2);

    for (int l = 0; l < 3; l++) {
        if (l > 0) {
            k_fuse<<<130, 256>>>(Wk, bk, Wq, bq, Wv, bv, Ar, Mr, l);
            k_packW<<<64, 256>>>();
            k_proj_mma<<<512, 256, SMEM_MMA2>>>(0);
            k_proj_mma<<<512, 256, SMEM_MMA2>>>(1);
        }
        k_packWa<<<16, 256>>>(Wa, l);
        k_edge<0, 0><<<16384, 256>>>(pr, l);   // A -> B, writes gAggB
        k_edge<1, 0><<<16384, 256>>>(pr, l);   // B -> A, writes gAggA
        k_edge<2, 1><<<16384, 256>>>(pr, l);   // A -> A, accumulates gAggA
        k_out_mma<<<512, 256, SMEM_MMA2>>>(0, ba, skip, l);
        k_out_mma<<<512, 256, SMEM_MMA2>>>(1, ba, skip, l);
    }

    k_zero_out<<<1, 1>>>((float*)d_out);
    k_final<<<1024, 256>>>(lw, lb, (float*)d_out);
}

// round 15
// speedup vs baseline: 1.0437x; 1.0437x over previous
#include <cuda_runtime.h>
#include <cuda_bf16.h>
#include <cstdint>
#include <math.h>

#define NN 131072
#define EE 1000000
#define XST 132          // transposed-X smem stride (floats), k_out2
#define WST 72           // W smem stride (floats), k_out2
#define SMEM_BYTES ((64 * XST + 64 * WST + 64) * 4)

// proj mma smem layout (u32 units), 256-row block
#define U2_AH   0        // 256 * 36
#define U2_AL   9216
#define U2_BH   18432    // 64 * 36
#define U2_BL   20736
#define U2_BIAS 23040    // 320 floats
#define SMEM_MMA2 ((23040 + 320) * 4)

#ifdef CUDA_API_PER_THREAD_DEFAULT_STREAM
#define MAIN_STREAM cudaStreamPerThread
#else
#define MAIN_STREAM cudaStreamLegacy
#endif

typedef unsigned long long u64;

// ---------------- static device scratch ----------------
__device__ __align__(128) float gXA[NN * 64];
__device__ __align__(128) float gXB[NN * 64];
__device__ __align__(128) float gBufA[(size_t)NN * 320]; // [q | rel0 kv | rel2 kv]
__device__ __align__(128) float gBufB[(size_t)NN * 192]; // [q | rel1 kv]
__device__ __align__(128) float gAggA[NN * 64];
__device__ __align__(128) float gAggB[NN * 64];
__device__ __align__(128) float gWfA[64 * 320];
__device__ float gBfA[320];
__device__ __align__(128) float gWfB[64 * 192];
__device__ float gBfB[192];
// packed W (bf16 hi/lo pairs), B-frag order: [col][kpair]
__device__ __align__(128) uint32_t gWAh[320 * 32];
__device__ __align__(128) uint32_t gWAl[320 * 32];
__device__ __align__(128) uint32_t gWBh[192 * 32];
__device__ __align__(128) uint32_t gWBl[192 * 32];
__device__ int   gRowptr[3][NN + 1];
__device__ int   gCur3[3][NN];
__device__ int   gBlkSum[3][128];
__device__ int   gCsr[3][EE];

// ---------------- packed f32x2 helpers ----------------
__device__ __forceinline__ u64 packf2(float x, float y) {
    u64 r; asm("mov.b64 %0, {%1, %2};" : "=l"(r) : "f"(x), "f"(y)); return r;
}
__device__ __forceinline__ void fma2(u64& d, u64 a, u64 b) {
    asm("fma.rn.f32x2 %0, %1, %2, %0;" : "+l"(d) : "l"(a), "l"(b));
}
__device__ __forceinline__ u64 mul2(u64 a, u64 b) {
    u64 r; asm("mul.rn.f32x2 %0, %1, %2;" : "=l"(r) : "l"(a), "l"(b)); return r;
}

// ---------------- bf16 split helper ----------------
__device__ __forceinline__ uint32_t pack_bf16_hi(float a, float b, uint32_t& lo_out) {
    __nv_bfloat16 ha = __float2bfloat16_rn(a);
    __nv_bfloat16 hb = __float2bfloat16_rn(b);
    __nv_bfloat16 la = __float2bfloat16_rn(a - __bfloat162float(ha));
    __nv_bfloat16 lb = __float2bfloat16_rn(b - __bfloat162float(hb));
    unsigned short uha = *(unsigned short*)&ha, uhb = *(unsigned short*)&hb;
    unsigned short ula = *(unsigned short*)&la, ulb = *(unsigned short*)&lb;
    lo_out = (uint32_t)ula | ((uint32_t)ulb << 16);
    return (uint32_t)uha | ((uint32_t)uhb << 16);
}

// m16n8k16 bf16 MMA, f32 accum
__device__ __forceinline__ void mma16816(float* c, const uint32_t* a, const uint32_t* b) {
    asm volatile(
        "mma.sync.aligned.m16n8k16.row.col.f32.bf16.bf16.f32 "
        "{%0,%1,%2,%3}, {%4,%5,%6,%7}, {%8,%9}, {%0,%1,%2,%3};"
        : "+f"(c[0]), "+f"(c[1]), "+f"(c[2]), "+f"(c[3])
        : "r"(a[0]), "r"(a[1]), "r"(a[2]), "r"(a[3]), "r"(b[0]), "r"(b[1]));
}

// ---------------- misc ----------------
__device__ __forceinline__ float warpsum(float p) {
    p += __shfl_xor_sync(0xffffffffu, p, 16);
    p += __shfl_xor_sync(0xffffffffu, p, 8);
    p += __shfl_xor_sync(0xffffffffu, p, 4);
    p += __shfl_xor_sync(0xffffffffu, p, 2);
    p += __shfl_xor_sync(0xffffffffu, p, 1);
    return p;
}
__device__ __forceinline__ void warpsum2(float& a, float& b) {
#pragma unroll
    for (int o = 16; o; o >>= 1) {
        a += __shfl_xor_sync(0xffffffffu, a, o);
        b += __shfl_xor_sync(0xffffffffu, b, o);
    }
}
__device__ __forceinline__ int wscan_incl(int x, int lane) {
#pragma unroll
    for (int o = 1; o < 32; o <<= 1) {
        int y = __shfl_up_sync(0xffffffffu, x, o);
        if (lane >= o) x += y;
    }
    return x;
}
__device__ __forceinline__ float gelu_f(float v) {
    return 0.5f * v * (1.0f + erff(v * 0.7071067811865476f));
}
__device__ __forceinline__ void online_upd(float sc, float vz, float vw,
                                           float& mx, float& den, float& s0, float& s1) {
    if (sc > mx) {
        float f = __expf(mx - sc);
        den = den * f + 1.f;
        s0  = s0 * f + vz;
        s1  = s1 * f + vw;
        mx = sc;
    } else {
        float e = __expf(sc - mx);
        den += e;
        s0  += e * vz;
        s1  += e * vw;
    }
}

// ---------------- input staging ----------------
__global__ void k_copyin(const float* __restrict__ xA, const float* __restrict__ xB) {
    int i = blockIdx.x * blockDim.x + threadIdx.x;
    gXA[i] = xA[i];
    gXB[i] = xB[i];
}

// ---------------- CSR build ----------------
__global__ void k_zero_deg() {
    int rel = blockIdx.y;
    int i = blockIdx.x * blockDim.x + threadIdx.x;
    if (i < NN) gRowptr[rel][i] = 0;
}
__global__ void k_hist(const int* __restrict__ e0, const int* __restrict__ e1,
                       const int* __restrict__ e2) {
    int rel = blockIdx.y;
    const int* ei = rel == 0 ? e0 : rel == 1 ? e1 : e2;
    int e = blockIdx.x * blockDim.x + threadIdx.x;
    if (e < EE) atomicAdd(&gRowptr[rel][ei[EE + e]], 1);
}
__global__ void k_blocksum() {
    int rel = blockIdx.y;
    int i = blockIdx.x * 1024 + threadIdx.x;
    int lane = threadIdx.x & 31, wid = threadIdx.x >> 5;
    int s = gRowptr[rel][i];
#pragma unroll
    for (int o = 16; o; o >>= 1) s += __shfl_xor_sync(0xffffffffu, s, o);
    __shared__ int sh[32];
    if (lane == 0) sh[wid] = s;
    __syncthreads();
    if (wid == 0) {
        int t = sh[lane];
#pragma unroll
        for (int o = 16; o; o >>= 1) t += __shfl_xor_sync(0xffffffffu, t, o);
        if (lane == 0) gBlkSum[rel][blockIdx.x] = t;
    }
}
__global__ void k_scanblk() {
    int tid = threadIdx.x, lane = tid & 31, wid = tid >> 5;
    __shared__ int ws[4];
    for (int rel = 0; rel < 3; rel++) {
        int v = gBlkSum[rel][tid];
        int x = wscan_incl(v, lane);
        __syncthreads();
        if (lane == 31) ws[wid] = x;
        __syncthreads();
        int add = 0;
#pragma unroll
        for (int w = 0; w < 4; w++) add += (w < wid) ? ws[w] : 0;
        gBlkSum[rel][tid] = x + add - v;
        __syncthreads();
    }
}
__global__ void k_scanlocal() {
    int rel = blockIdx.y;
    int idx = blockIdx.x * 1024 + threadIdx.x;
    int lane = threadIdx.x & 31, wid = threadIdx.x >> 5;
    int v = gRowptr[rel][idx];
    int x = wscan_incl(v, lane);
    __shared__ int ws[32];
    if (lane == 31) ws[wid] = x;
    __syncthreads();
    if (wid == 0) ws[lane] = wscan_incl(ws[lane], lane);
    __syncthreads();
    int incl = x + (wid ? ws[wid - 1] : 0);
    int excl = incl - v + gBlkSum[rel][blockIdx.x];
    gRowptr[rel][idx] = excl;
    gCur3[rel][idx] = excl;
    if (idx == NN - 1) gRowptr[rel][NN] = excl + v;
}
__global__ void k_scatter(const int* __restrict__ e0, const int* __restrict__ e1,
                          const int* __restrict__ e2) {
    int rel = blockIdx.y;
    const int* ei = rel == 0 ? e0 : rel == 1 ? e1 : e2;
    int e = blockIdx.x * blockDim.x + threadIdx.x;
    if (e >= EE) return;
    int dst = ei[EE + e];
    int pos = atomicAdd(&gCur3[rel][dst], 1);
    gCsr[rel][pos] = ei[e];
}

// ---------------- per-layer fused weight build ----------------
__device__ float fuse_elem(int typ, int i, int j, int l,
                           const float* __restrict__ Wk, const float* __restrict__ bk,
                           const float* __restrict__ Wq, const float* __restrict__ bq,
                           const float* __restrict__ Wv, const float* __restrict__ bv,
                           const float* __restrict__ Ar, const float* __restrict__ Mr) {
    if (j < 64) {
        if (i >= 0) return Wq[(size_t)(l * 2 + typ) * 4096 + i * 64 + j];
        return bq[(l * 2 + typ) * 64 + j];
    }
    int t = j - 64, rel;
    if (typ == 0) { rel = (t >> 7) ? 2 : 0; t &= 127; }
    else rel = 1;
    int lane = t >> 2, c = t & 3;
    int isK = (c < 2);
    int dcol = 2 * lane + (c & 1);
    const float* R = (isK ? Ar : Mr) + (size_t)(l * 3 + rel) * 4096;
    float s = 0.f;
    if (i >= 0) {
        const float* w = (isK ? Wk : Wv) + (size_t)(l * 2 + typ) * 4096 + i * 64;
#pragma unroll
        for (int d = 0; d < 64; d++) s += w[d] * R[d * 64 + dcol];
    } else {
        const float* b = (isK ? bk : bv) + (l * 2 + typ) * 64;
#pragma unroll
        for (int d = 0; d < 64; d++) s += b[d] * R[d * 64 + dcol];
    }
    return s;
}
__global__ void k_fuse(const float* __restrict__ Wk, const float* __restrict__ bk,
                       const float* __restrict__ Wq, const float* __restrict__ bq,
                       const float* __restrict__ Wv, const float* __restrict__ bv,
                       const float* __restrict__ Ar, const float* __restrict__ Mr, int l) {
    int id = blockIdx.x * blockDim.x + threadIdx.x;
    if (id < 20480) {
        int i = id / 320, j = id % 320;
        gWfA[id] = fuse_elem(0, i, j, l, Wk, bk, Wq, bq, Wv, bv, Ar, Mr);
    } else if (id < 32768) {
        int idx = id - 20480;
        int i = idx / 192, j = idx % 192;
        gWfB[idx] = fuse_elem(1, i, j, l, Wk, bk, Wq, bq, Wv, bv, Ar, Mr);
    } else if (id < 33088) {
        int j = id - 32768;
        gBfA[j] = fuse_elem(0, -1, j, l, Wk, bk, Wq, bq, Wv, bv, Ar, Mr);
    } else if (id < 33280) {
        int j = id - 33088;
        gBfB[j] = fuse_elem(1, -1, j, l, Wk, bk, Wq, bq, Wv, bv, Ar, Mr);
    }
}

// ---------------- pack W once per layer into B-frag order ------------------
__global__ void k_packW() {
    int id = blockIdx.x * blockDim.x + threadIdx.x;
    if (id < 320 * 32) {
        int col = id >> 5, kp = id & 31;
        uint32_t lo, hi = pack_bf16_hi(gWfA[(2 * kp) * 320 + col],
                                       gWfA[(2 * kp + 1) * 320 + col], lo);
        gWAh[id] = hi;
        gWAl[id] = lo;
    } else if (id < 320 * 32 + 192 * 32) {
        int idx = id - 320 * 32;
        int col = idx >> 5, kp = idx & 31;
        uint32_t lo, hi = pack_bf16_hi(gWfB[(2 * kp) * 192 + col],
                                       gWfB[(2 * kp + 1) * 192 + col], lo);
        gWBh[idx] = hi;
        gWBl[idx] = lo;
    }
}

// ---------------- HMMA projection: 256 rows/block, loop over col groups ----
__global__ void __launch_bounds__(256, 2) k_proj_mma(int typ) {
    extern __shared__ uint32_t su[];
    const float* X   = typ ? gXB  : gXA;
    const uint32_t* WH = typ ? gWBh : gWAh;
    const uint32_t* WL = typ ? gWBl : gWAl;
    const float* Bf  = typ ? gBfB : gBfA;
    float*       Out = typ ? gBufB : gBufA;
    const int OC = typ ? 192 : 320;
    const int NCG = typ ? 3 : 5;

    uint32_t* AH = su + U2_AH;
    uint32_t* AL = su + U2_AL;
    uint32_t* BH = su + U2_BH;
    uint32_t* BL = su + U2_BL;
    float*    Bs = (float*)(su + U2_BIAS);

    int tid = threadIdx.x;
    size_t row0 = (size_t)blockIdx.x * 256;

    {
        const float4* xr = (const float4*)(X + (row0 + tid) * 64);
        int rb = tid * 36;
#pragma unroll
        for (int j = 0; j < 16; j++) {
            float4 v = xr[j];
            uint32_t lo0, lo1;
            uint32_t hi0 = pack_bf16_hi(v.x, v.y, lo0);
            uint32_t hi1 = pack_bf16_hi(v.z, v.w, lo1);
            AH[rb + 2 * j]     = hi0;
            AH[rb + 2 * j + 1] = hi1;
            AL[rb + 2 * j]     = lo0;
            AL[rb + 2 * j + 1] = lo1;
        }
    }
    for (int i = tid; i < OC; i += 256) Bs[i] = Bf[i];

    int w = tid >> 5, lid = tid & 31, g = lid >> 2, tig = lid & 3;
    int mo = w * 32;

    for (int cg = 0; cg < NCG; cg++) {
        int col0 = cg * 64;
        __syncthreads();
        for (int i = tid; i < 2048; i += 256) {
            int n = i >> 5, kp = i & 31;
            BH[n * 36 + kp] = WH[(size_t)(col0 + n) * 32 + kp];
            BL[n * 36 + kp] = WL[(size_t)(col0 + n) * 32 + kp];
        }
        __syncthreads();

        float c[2][8][4];
#pragma unroll
        for (int nt = 0; nt < 8; nt++) {
            float b0 = Bs[col0 + nt * 8 + tig * 2];
            float b1 = Bs[col0 + nt * 8 + tig * 2 + 1];
#pragma unroll
            for (int mt = 0; mt < 2; mt++) {
                c[mt][nt][0] = b0; c[mt][nt][1] = b1;
                c[mt][nt][2] = b0; c[mt][nt][3] = b1;
            }
        }

#pragma unroll
        for (int s = 0; s < 3; s++) {
            const uint32_t* Aa = (s < 2) ? AH : AL;
            const uint32_t* Ba = (s == 1) ? BL : BH;
#pragma unroll
            for (int ks = 0; ks < 4; ks++) {
                int ab = (mo + g) * 36 + ks * 8 + tig;
                uint32_t a[2][4];
                a[0][0] = Aa[ab];        a[0][2] = Aa[ab + 4];
                a[0][1] = Aa[ab + 288];  a[0][3] = Aa[ab + 292];
                a[1][0] = Aa[ab + 576];  a[1][2] = Aa[ab + 580];
                a[1][1] = Aa[ab + 864];  a[1][3] = Aa[ab + 868];
                int bb = g * 36 + ks * 8 + tig;
                uint32_t b[8][2];
#pragma unroll
                for (int nt = 0; nt < 8; nt++) {
                    b[nt][0] = Ba[bb + nt * 288];
                    b[nt][1] = Ba[bb + nt * 288 + 4];
                }
#pragma unroll
                for (int mt = 0; mt < 2; mt++)
#pragma unroll
                    for (int nt = 0; nt < 8; nt++)
                        mma16816(c[mt][nt], a[mt], b[nt]);
            }
        }

#pragma unroll
        for (int mt = 0; mt < 2; mt++) {
            size_t ra = row0 + mo + mt * 16 + g;
#pragma unroll
            for (int nt = 0; nt < 8; nt++) {
                float* p = Out + ra * OC + col0 + nt * 8 + tig * 2;
                *(float2*)p = make_float2(c[mt][nt][0], c[mt][nt][1]);
                *(float2*)(p + 8 * (size_t)OC) = make_float2(c[mt][nt][2], c[mt][nt][3]);
            }
        }
    }
}

// ---------------- blocked output projection + gelu + skip (FFMA2) ----------
__global__ void __launch_bounds__(128) k_out2(int typ, const float* __restrict__ Wa,
                                              const float* __restrict__ ba,
                                              const float* __restrict__ skip, int l) {
    extern __shared__ float smf[];
    const float* agg = typ ? gAggB : gAggA;
    float* X = typ ? gXB : gXA;
    const float* w = Wa + (size_t)(l * 2 + typ) * 4096;

    float* Xs = smf;
    float* Ws = smf + 64 * XST;
    float* Bs = smf + 64 * XST + 64 * WST;

    int tid = threadIdx.x;
    size_t row0 = (size_t)blockIdx.x * 128;

    for (int i = tid; i < 4096; i += 128) {
        int k = i >> 6, col = i & 63;
        Ws[k * WST + col + ((col >> 5) << 2)] = w[k * 64 + col];
    }
    if (tid < 64) Bs[tid] = ba[(l * 2 + typ) * 64 + tid];

    const float4* A4 = (const float4*)(agg + row0 * 64);
#pragma unroll
    for (int i = 0; i < 16; i++) {
        int idx = i * 128 + tid;
        int row = idx >> 4, kq = idx & 15;
        float4 v = A4[idx];
        Xs[(4 * kq + 0) * XST + row] = gelu_f(v.x);
        Xs[(4 * kq + 1) * XST + row] = gelu_f(v.y);
        Xs[(4 * kq + 2) * XST + row] = gelu_f(v.z);
        Xs[(4 * kq + 3) * XST + row] = gelu_f(v.w);
    }
    __syncthreads();

    int tc = tid & 7, tr = tid >> 3;
    int cb = tc * 8 + ((tc >> 2) << 2);
    int rb = tr * 8;

    u64 acc[8][4];
#pragma unroll
    for (int cp = 0; cp < 4; cp++) {
        u64 b = packf2(Bs[tc * 8 + 2 * cp], Bs[tc * 8 + 2 * cp + 1]);
#pragma unroll
        for (int r = 0; r < 8; r++) acc[r][cp] = b;
    }

#pragma unroll 4
    for (int k = 0; k < 64; k++) {
        float4 xa = *(const float4*)(Xs + k * XST + rb);
        float4 xb = *(const float4*)(Xs + k * XST + rb + 4);
        ulonglong2 wA = *(const ulonglong2*)(Ws + k * WST + cb);
        ulonglong2 wB = *(const ulonglong2*)(Ws + k * WST + cb + 4);
        float xr[8] = {xa.x, xa.y, xa.z, xa.w, xb.x, xb.y, xb.z, xb.w};
#pragma unroll
        for (int r = 0; r < 8; r++) {
            u64 xx = packf2(xr[r], xr[r]);
            fma2(acc[r][0], wA.x, xx);
            fma2(acc[r][1], wA.y, xx);
            fma2(acc[r][2], wB.x, xx);
            fma2(acc[r][3], wB.y, xx);
        }
    }

    float sg = 1.0f / (1.0f + __expf(-skip[l * 2 + typ]));
    float omg = 1.0f - sg;
    u64 sgp = packf2(sg, sg), omgp = packf2(omg, omg);

#pragma unroll
    for (int r = 0; r < 8; r++) {
        float* xp = X + (row0 + rb + r) * 64 + tc * 8;
        ulonglong2 xo = *(ulonglong2*)xp;
        ulonglong2 xo2 = *(ulonglong2*)(xp + 4);
        u64 y0 = mul2(xo.x,  omgp); fma2(y0, acc[r][0], sgp);
        u64 y1 = mul2(xo.y,  omgp); fma2(y1, acc[r][1], sgp);
        u64 y2 = mul2(xo2.x, omgp); fma2(y2, acc[r][2], sgp);
        u64 y3 = mul2(xo2.y, omgp); fma2(y3, acc[r][3], sgp);
        ulonglong2 s0; s0.x = y0; s0.y = y1;
        ulonglong2 s1; s1.x = y2; s1.y = y3;
        *(ulonglong2*)xp = s0;
        *(ulonglong2*)(xp + 4) = s1;
    }
}

// ---------------- edge attention: TWO-STREAM online softmax ----------------
template <int REL, int ACCUM>
__global__ void k_edge(const float* __restrict__ p_rel, int l) {
    int t = blockIdx.x * blockDim.x + threadIdx.x;
    int gw = t >> 5, lane = t & 31;
    if (gw >= NN) return;

    const float* Q;   int qs;
    const float* Src; int ss, off;
    float* Agg;
    if (REL == 0) { Q = gBufB; qs = 192; Src = gBufA; ss = 320; off = 64;  Agg = gAggB; }
    else if (REL == 1) { Q = gBufA; qs = 320; Src = gBufB; ss = 192; off = 64;  Agg = gAggA; }
    else { Q = gBufA; qs = 320; Src = gBufA; ss = 320; off = 192; Agg = gAggA; }

    float scl = p_rel[l * 3 + REL] * 0.125f;
    float2 q = *(const float2*)(Q + (size_t)gw * qs + 2 * lane);

    const int* __restrict__ rowptr = gRowptr[REL];
    const int* __restrict__ csr = gCsr[REL];
    int beg = rowptr[gw], end = rowptr[gw + 1];

    float mxA = -3.0e38f, denA = 0.f, s0A = 0.f, s1A = 0.f;
    float mxB = -3.0e38f, denB = 0.f, s0B = 0.f, s1B = 0.f;

    int j = beg;
    for (; j + 2 <= end; j += 2) {
        int sA = __ldg(&csr[j]);
        int sB = __ldg(&csr[j + 1]);
        float4 kvA = *(const float4*)(Src + (size_t)sA * ss + off + 4 * lane);
        float4 kvB = *(const float4*)(Src + (size_t)sB * ss + off + 4 * lane);
        float pA = fmaf(q.x, kvA.x, q.y * kvA.y);
        float pB = fmaf(q.x, kvB.x, q.y * kvB.y);
        warpsum2(pA, pB);
        online_upd(pA * scl, kvA.z, kvA.w, mxA, denA, s0A, s1A);
        online_upd(pB * scl, kvB.z, kvB.w, mxB, denB, s0B, s1B);
    }
    if (j < end) {
        int s = __ldg(&csr[j]);
        float4 kv = *(const float4*)(Src + (size_t)s * ss + off + 4 * lane);
        float sc = warpsum(fmaf(q.x, kv.x, q.y * kv.y)) * scl;
        online_upd(sc, kv.z, kv.w, mxA, denA, s0A, s1A);
    }

    float a0 = 0.f, a1 = 0.f;
    {
        float m = fmaxf(mxA, mxB);
        float fA = __expf(mxA - m), fB = __expf(mxB - m);
        float den = denA * fA + denB * fB;
        float s0 = s0A * fA + s0B * fB;
        float s1 = s1A * fA + s1B * fB;
        if (den > 0.f) {
            float inv = 1.0f / den;
            a0 = s0 * inv;
            a1 = s1 * inv;
        }
    }
    float2* ap = (float2*)(Agg + (size_t)gw * 64 + 2 * lane);
    if (ACCUM) {
        float2 old = *ap;
        *ap = make_float2(old.x + a0, old.y + a1);
    } else {
        *ap = make_float2(a0, a1);
    }
}

// ---------------- final pool + linear ----------------
__global__ void k_zero_out(float* out) { out[0] = 0.f; }

__global__ void k_final(const float* __restrict__ lw, const float* __restrict__ lb,
                        float* out) {
    float acc = 0.f;
    const int total = 2 * NN * 64;
    for (int i = blockIdx.x * blockDim.x + threadIdx.x; i < total;
         i += gridDim.x * blockDim.x) {
        float v = (i < NN * 64) ? gXA[i] : gXB[i - NN * 64];
        acc += v * lw[i & 63];
    }
    __shared__ float red[256];
    red[threadIdx.x] = acc;
    __syncthreads();
    for (int s = 128; s; s >>= 1) {
        if (threadIdx.x < s) red[threadIdx.x] += red[threadIdx.x + s];
        __syncthreads();
    }
    if (threadIdx.x == 0) {
        float v = red[0];
        if (blockIdx.x == 0) v += lb[0];
        atomicAdd(out, v);
    }
}

// ---------------- launch ----------------
extern "C" void kernel_launch(void* const* d_in, const int* in_sizes, int n_in,
                              void* d_out, int out_size) {
    const float* xA   = (const float*)d_in[0];
    const float* xB   = (const float*)d_in[1];
    const float* Wk   = (const float*)d_in[2];
    const float* bk   = (const float*)d_in[3];
    const float* Wq   = (const float*)d_in[4];
    const float* bq   = (const float*)d_in[5];
    const float* Wv   = (const float*)d_in[6];
    const float* bv   = (const float*)d_in[7];
    const float* Ar   = (const float*)d_in[8];
    const float* Mr   = (const float*)d_in[9];
    const float* pr   = (const float*)d_in[10];
    const float* Wa   = (const float*)d_in[11];
    const float* ba   = (const float*)d_in[12];
    const float* skip = (const float*)d_in[13];
    const float* lw   = (const float*)d_in[14];
    const float* lb   = (const float*)d_in[15];
    const int* e0 = (const int*)d_in[16];
    const int* e1 = (const int*)d_in[17];
    const int* e2 = (const int*)d_in[18];

    // one-time stream/event setup (host-side only; no device allocations)
    static cudaStream_t sAux = nullptr;
    static cudaEvent_t evFork, evCsr, evA[3], evB[3];
    if (!sAux) {
        cudaStreamCreateWithFlags(&sAux, cudaStreamNonBlocking);
        cudaEventCreateWithFlags(&evFork, cudaEventDisableTiming);
        cudaEventCreateWithFlags(&evCsr, cudaEventDisableTiming);
        for (int i = 0; i < 3; i++) {
            cudaEventCreateWithFlags(&evA[i], cudaEventDisableTiming);
            cudaEventCreateWithFlags(&evB[i], cudaEventDisableTiming);
        }
        cudaFuncSetAttribute(k_proj_mma, cudaFuncAttributeMaxDynamicSharedMemorySize, SMEM_MMA2);
        cudaFuncSetAttribute(k_out2, cudaFuncAttributeMaxDynamicSharedMemorySize, SMEM_BYTES);
        cudaFuncSetAttribute(k_proj_mma, cudaFuncAttributePreferredSharedMemoryCarveout, 100);
        cudaFuncSetAttribute(k_out2, cudaFuncAttributePreferredSharedMemoryCarveout, 100);
    }

    // fork aux stream; CSR build runs concurrently with layer-0 GEMMs
    cudaEventRecord(evFork, MAIN_STREAM);
    cudaStreamWaitEvent(sAux, evFork, 0);
    k_zero_deg<<<dim3(NN / 256, 3), 256, 0, sAux>>>();
    k_hist<<<dim3((EE + 255) / 256, 3), 256, 0, sAux>>>(e0, e1, e2);
    k_blocksum<<<dim3(128, 3), 1024, 0, sAux>>>();
    k_scanblk<<<1, 128, 0, sAux>>>();
    k_scanlocal<<<dim3(128, 3), 1024, 0, sAux>>>();
    k_scatter<<<dim3((EE + 255) / 256, 3), 256, 0, sAux>>>(e0, e1, e2);
    cudaEventRecord(evCsr, sAux);

    // main stream: layer-0 GEMMs
    k_copyin<<<NN * 64 / 256, 256>>>(xA, xB);
    k_fuse<<<130, 256>>>(Wk, bk, Wq, bq, Wv, bv, Ar, Mr, 0);
    k_packW<<<64, 256>>>();
    k_proj_mma<<<512, 256, SMEM_MMA2>>>(0);
    k_proj_mma<<<512, 256, SMEM_MMA2>>>(1);
    cudaStreamWaitEvent(MAIN_STREAM, evCsr, 0);

    for (int l = 0; l < 3; l++) {
        if (l > 0) {
            k_fuse<<<130, 256>>>(Wk, bk, Wq, bq, Wv, bv, Ar, Mr, l);
            k_packW<<<64, 256>>>();
            k_proj_mma<<<512, 256, SMEM_MMA2>>>(0);
            cudaStreamWaitEvent(MAIN_STREAM, evB[l - 1], 0);  // gXB ready, gAggB free
            k_proj_mma<<<512, 256, SMEM_MMA2>>>(1);
        }
        // rel0 fills gAggB -> k_out2(1) forks to aux, overlapped with rel1/rel2
        k_edge<0, 0><<<16384, 256>>>(pr, l);
        cudaEventRecord(evA[l], MAIN_STREAM);
        cudaStreamWaitEvent(sAux, evA[l], 0);
        k_out2<<<1024, 128, SMEM_BYTES, sAux>>>(1, Wa, ba, skip, l);
        cudaEventRecord(evB[l], sAux);

        k_edge<1, 0><<<16384, 256>>>(pr, l);
        k_edge<2, 1><<<16384, 256>>>(pr, l);
        k_out2<<<1024, 128, SMEM_BYTES>>>(0, Wa, ba, skip, l);
    }

    cudaStreamWaitEvent(MAIN_STREAM, evB[2], 0);   // join aux before readout
    k_zero_out<<<1, 1>>>((float*)d_out);
    k_final<<<1024, 256>>>(lw, lb, (float*)d_out);
}

// round 16
// speedup vs baseline: 1.1038x; 1.0577x over previous
#include <cuda_runtime.h>
#include <cuda_bf16.h>
#include <cstdint>
#include <math.h>

#define NN 131072
#define EE 1000000
#define XST 132          // transposed-X smem stride (floats), k_out2
#define WST 72           // W smem stride (floats), k_out2
#define SMEM_BYTES ((64 * XST + 64 * WST + 64) * 4)

// proj mma smem layout (u32 units), 256-row block
#define U2_AH   0        // 256 * 36
#define U2_AL   9216
#define U2_BH   18432    // 64 * 36
#define U2_BL   20736
#define U2_BIAS 23040    // 320 floats
#define SMEM_MMA2 ((23040 + 320) * 4)

#ifdef CUDA_API_PER_THREAD_DEFAULT_STREAM
#define MAIN_STREAM cudaStreamPerThread
#else
#define MAIN_STREAM cudaStreamLegacy
#endif

typedef unsigned long long u64;

// ---------------- static device scratch ----------------
__device__ __align__(128) float gXA[NN * 64];
__device__ __align__(128) float gXB[NN * 64];
__device__ __align__(128) float gBufA[(size_t)NN * 320]; // [q | rel0 kv | rel2 kv]
__device__ __align__(128) float gBufB[(size_t)NN * 192]; // [q | rel1 kv]
__device__ __align__(128) float gAggA[NN * 64];
__device__ __align__(128) float gAggB[NN * 64];
__device__ __align__(128) float gWfA[64 * 320];
__device__ float gBfA[320];
__device__ __align__(128) float gWfB[64 * 192];
__device__ float gBfB[192];
// packed W (bf16 hi/lo pairs), B-frag order: [col][kpair]
__device__ __align__(128) uint32_t gWAh[320 * 32];
__device__ __align__(128) uint32_t gWAl[320 * 32];
__device__ __align__(128) uint32_t gWBh[192 * 32];
__device__ __align__(128) uint32_t gWBl[192 * 32];
__device__ int   gRowptr[3][NN + 1];
__device__ int   gCur3[3][NN];
__device__ int   gBlkSum[3][128];
__device__ int   gCsr[3][EE];

// ---------------- packed f32x2 helpers ----------------
__device__ __forceinline__ u64 packf2(float x, float y) {
    u64 r; asm("mov.b64 %0, {%1, %2};" : "=l"(r) : "f"(x), "f"(y)); return r;
}
__device__ __forceinline__ void fma2(u64& d, u64 a, u64 b) {
    asm("fma.rn.f32x2 %0, %1, %2, %0;" : "+l"(d) : "l"(a), "l"(b));
}
__device__ __forceinline__ u64 mul2(u64 a, u64 b) {
    u64 r; asm("mul.rn.f32x2 %0, %1, %2;" : "=l"(r) : "l"(a), "l"(b)); return r;
}

// ---------------- bf16 split helper ----------------
__device__ __forceinline__ uint32_t pack_bf16_hi(float a, float b, uint32_t& lo_out) {
    __nv_bfloat16 ha = __float2bfloat16_rn(a);
    __nv_bfloat16 hb = __float2bfloat16_rn(b);
    __nv_bfloat16 la = __float2bfloat16_rn(a - __bfloat162float(ha));
    __nv_bfloat16 lb = __float2bfloat16_rn(b - __bfloat162float(hb));
    unsigned short uha = *(unsigned short*)&ha, uhb = *(unsigned short*)&hb;
    unsigned short ula = *(unsigned short*)&la, ulb = *(unsigned short*)&lb;
    lo_out = (uint32_t)ula | ((uint32_t)ulb << 16);
    return (uint32_t)uha | ((uint32_t)uhb << 16);
}

// m16n8k16 bf16 MMA, f32 accum
__device__ __forceinline__ void mma16816(float* c, const uint32_t* a, const uint32_t* b) {
    asm volatile(
        "mma.sync.aligned.m16n8k16.row.col.f32.bf16.bf16.f32 "
        "{%0,%1,%2,%3}, {%4,%5,%6,%7}, {%8,%9}, {%0,%1,%2,%3};"
        : "+f"(c[0]), "+f"(c[1]), "+f"(c[2]), "+f"(c[3])
        : "r"(a[0]), "r"(a[1]), "r"(a[2]), "r"(a[3]), "r"(b[0]), "r"(b[1]));
}

// ---------------- misc ----------------
__device__ __forceinline__ float warpsum(float p) {
    p += __shfl_xor_sync(0xffffffffu, p, 16);
    p += __shfl_xor_sync(0xffffffffu, p, 8);
    p += __shfl_xor_sync(0xffffffffu, p, 4);
    p += __shfl_xor_sync(0xffffffffu, p, 2);
    p += __shfl_xor_sync(0xffffffffu, p, 1);
    return p;
}
__device__ __forceinline__ void warpsum2(float& a, float& b) {
#pragma unroll
    for (int o = 16; o; o >>= 1) {
        a += __shfl_xor_sync(0xffffffffu, a, o);
        b += __shfl_xor_sync(0xffffffffu, b, o);
    }
}
__device__ __forceinline__ int wscan_incl(int x, int lane) {
#pragma unroll
    for (int o = 1; o < 32; o <<= 1) {
        int y = __shfl_up_sync(0xffffffffu, x, o);
        if (lane >= o) x += y;
    }
    return x;
}
__device__ __forceinline__ float gelu_f(float v) {
    return 0.5f * v * (1.0f + erff(v * 0.7071067811865476f));
}
__device__ __forceinline__ void online_upd(float sc, float vz, float vw,
                                           float& mx, float& den, float& s0, float& s1) {
    if (sc > mx) {
        float f = __expf(mx - sc);
        den = den * f + 1.f;
        s0  = s0 * f + vz;
        s1  = s1 * f + vw;
        mx = sc;
    } else {
        float e = __expf(sc - mx);
        den += e;
        s0  += e * vz;
        s1  += e * vw;
    }
}

// ---------------- input staging ----------------
__global__ void k_copyin(const float* __restrict__ xA, const float* __restrict__ xB) {
    int i = blockIdx.x * blockDim.x + threadIdx.x;
    gXA[i] = xA[i];
    gXB[i] = xB[i];
}

// ---------------- CSR build ----------------
__global__ void k_zero_deg() {
    int rel = blockIdx.y;
    int i = blockIdx.x * blockDim.x + threadIdx.x;
    if (i < NN) gRowptr[rel][i] = 0;
}
__global__ void k_hist(const int* __restrict__ e0, const int* __restrict__ e1,
                       const int* __restrict__ e2) {
    int rel = blockIdx.y;
    const int* ei = rel == 0 ? e0 : rel == 1 ? e1 : e2;
    int e = blockIdx.x * blockDim.x + threadIdx.x;
    if (e < EE) atomicAdd(&gRowptr[rel][ei[EE + e]], 1);
}
__global__ void k_blocksum() {
    int rel = blockIdx.y;
    int i = blockIdx.x * 1024 + threadIdx.x;
    int lane = threadIdx.x & 31, wid = threadIdx.x >> 5;
    int s = gRowptr[rel][i];
#pragma unroll
    for (int o = 16; o; o >>= 1) s += __shfl_xor_sync(0xffffffffu, s, o);
    __shared__ int sh[32];
    if (lane == 0) sh[wid] = s;
    __syncthreads();
    if (wid == 0) {
        int t = sh[lane];
#pragma unroll
        for (int o = 16; o; o >>= 1) t += __shfl_xor_sync(0xffffffffu, t, o);
        if (lane == 0) gBlkSum[rel][blockIdx.x] = t;
    }
}
__global__ void k_scanblk() {
    int tid = threadIdx.x, lane = tid & 31, wid = tid >> 5;
    __shared__ int ws[4];
    for (int rel = 0; rel < 3; rel++) {
        int v = gBlkSum[rel][tid];
        int x = wscan_incl(v, lane);
        __syncthreads();
        if (lane == 31) ws[wid] = x;
        __syncthreads();
        int add = 0;
#pragma unroll
        for (int w = 0; w < 4; w++) add += (w < wid) ? ws[w] : 0;
        gBlkSum[rel][tid] = x + add - v;
        __syncthreads();
    }
}
__global__ void k_scanlocal() {
    int rel = blockIdx.y;
    int idx = blockIdx.x * 1024 + threadIdx.x;
    int lane = threadIdx.x & 31, wid = threadIdx.x >> 5;
    int v = gRowptr[rel][idx];
    int x = wscan_incl(v, lane);
    __shared__ int ws[32];
    if (lane == 31) ws[wid] = x;
    __syncthreads();
    if (wid == 0) ws[lane] = wscan_incl(ws[lane], lane);
    __syncthreads();
    int incl = x + (wid ? ws[wid - 1] : 0);
    int excl = incl - v + gBlkSum[rel][blockIdx.x];
    gRowptr[rel][idx] = excl;
    gCur3[rel][idx] = excl;
    if (idx == NN - 1) gRowptr[rel][NN] = excl + v;
}
__global__ void k_scatter(const int* __restrict__ e0, const int* __restrict__ e1,
                          const int* __restrict__ e2) {
    int rel = blockIdx.y;
    const int* ei = rel == 0 ? e0 : rel == 1 ? e1 : e2;
    int e = blockIdx.x * blockDim.x + threadIdx.x;
    if (e >= EE) return;
    int dst = ei[EE + e];
    int pos = atomicAdd(&gCur3[rel][dst], 1);
    gCsr[rel][pos] = ei[e];
}

// ---------------- per-layer fused weight build ----------------
__device__ float fuse_elem(int typ, int i, int j, int l,
                           const float* __restrict__ Wk, const float* __restrict__ bk,
                           const float* __restrict__ Wq, const float* __restrict__ bq,
                           const float* __restrict__ Wv, const float* __restrict__ bv,
                           const float* __restrict__ Ar, const float* __restrict__ Mr) {
    if (j < 64) {
        if (i >= 0) return Wq[(size_t)(l * 2 + typ) * 4096 + i * 64 + j];
        return bq[(l * 2 + typ) * 64 + j];
    }
    int t = j - 64, rel;
    if (typ == 0) { rel = (t >> 7) ? 2 : 0; t &= 127; }
    else rel = 1;
    int lane = t >> 2, c = t & 3;
    int isK = (c < 2);
    int dcol = 2 * lane + (c & 1);
    const float* R = (isK ? Ar : Mr) + (size_t)(l * 3 + rel) * 4096;
    float s = 0.f;
    if (i >= 0) {
        const float* w = (isK ? Wk : Wv) + (size_t)(l * 2 + typ) * 4096 + i * 64;
#pragma unroll
        for (int d = 0; d < 64; d++) s += w[d] * R[d * 64 + dcol];
    } else {
        const float* b = (isK ? bk : bv) + (l * 2 + typ) * 64;
#pragma unroll
        for (int d = 0; d < 64; d++) s += b[d] * R[d * 64 + dcol];
    }
    return s;
}
__global__ void k_fuse(const float* __restrict__ Wk, const float* __restrict__ bk,
                       const float* __restrict__ Wq, const float* __restrict__ bq,
                       const float* __restrict__ Wv, const float* __restrict__ bv,
                       const float* __restrict__ Ar, const float* __restrict__ Mr, int l) {
    int id = blockIdx.x * blockDim.x + threadIdx.x;
    if (id < 20480) {
        int i = id / 320, j = id % 320;
        gWfA[id] = fuse_elem(0, i, j, l, Wk, bk, Wq, bq, Wv, bv, Ar, Mr);
    } else if (id < 32768) {
        int idx = id - 20480;
        int i = idx / 192, j = idx % 192;
        gWfB[idx] = fuse_elem(1, i, j, l, Wk, bk, Wq, bq, Wv, bv, Ar, Mr);
    } else if (id < 33088) {
        int j = id - 32768;
        gBfA[j] = fuse_elem(0, -1, j, l, Wk, bk, Wq, bq, Wv, bv, Ar, Mr);
    } else if (id < 33280) {
        int j = id - 33088;
        gBfB[j] = fuse_elem(1, -1, j, l, Wk, bk, Wq, bq, Wv, bv, Ar, Mr);
    }
}

// ---------------- pack W once per layer into B-frag order ------------------
__global__ void k_packW() {
    int id = blockIdx.x * blockDim.x + threadIdx.x;
    if (id < 320 * 32) {
        int col = id >> 5, kp = id & 31;
        uint32_t lo, hi = pack_bf16_hi(gWfA[(2 * kp) * 320 + col],
                                       gWfA[(2 * kp + 1) * 320 + col], lo);
        gWAh[id] = hi;
        gWAl[id] = lo;
    } else if (id < 320 * 32 + 192 * 32) {
        int idx = id - 320 * 32;
        int col = idx >> 5, kp = idx & 31;
        uint32_t lo, hi = pack_bf16_hi(gWfB[(2 * kp) * 192 + col],
                                       gWfB[(2 * kp + 1) * 192 + col], lo);
        gWBh[idx] = hi;
        gWBl[idx] = lo;
    }
}

// ---------------- HMMA projection: 256 rows/block, loop over col groups ----
__global__ void __launch_bounds__(256, 2) k_proj_mma(int typ) {
    extern __shared__ uint32_t su[];
    const float* X   = typ ? gXB  : gXA;
    const uint32_t* WH = typ ? gWBh : gWAh;
    const uint32_t* WL = typ ? gWBl : gWAl;
    const float* Bf  = typ ? gBfB : gBfA;
    float*       Out = typ ? gBufB : gBufA;
    const int OC = typ ? 192 : 320;
    const int NCG = typ ? 3 : 5;

    uint32_t* AH = su + U2_AH;
    uint32_t* AL = su + U2_AL;
    uint32_t* BH = su + U2_BH;
    uint32_t* BL = su + U2_BL;
    float*    Bs = (float*)(su + U2_BIAS);

    int tid = threadIdx.x;
    size_t row0 = (size_t)blockIdx.x * 256;

    {
        const float4* xr = (const float4*)(X + (row0 + tid) * 64);
        int rb = tid * 36;
#pragma unroll
        for (int j = 0; j < 16; j++) {
            float4 v = xr[j];
            uint32_t lo0, lo1;
            uint32_t hi0 = pack_bf16_hi(v.x, v.y, lo0);
            uint32_t hi1 = pack_bf16_hi(v.z, v.w, lo1);
            AH[rb + 2 * j]     = hi0;
            AH[rb + 2 * j + 1] = hi1;
            AL[rb + 2 * j]     = lo0;
            AL[rb + 2 * j + 1] = lo1;
        }
    }
    for (int i = tid; i < OC; i += 256) Bs[i] = Bf[i];

    int w = tid >> 5, lid = tid & 31, g = lid >> 2, tig = lid & 3;
    int mo = w * 32;

    for (int cg = 0; cg < NCG; cg++) {
        int col0 = cg * 64;
        __syncthreads();
        for (int i = tid; i < 2048; i += 256) {
            int n = i >> 5, kp = i & 31;
            BH[n * 36 + kp] = WH[(size_t)(col0 + n) * 32 + kp];
            BL[n * 36 + kp] = WL[(size_t)(col0 + n) * 32 + kp];
        }
        __syncthreads();

        float c[2][8][4];
#pragma unroll
        for (int nt = 0; nt < 8; nt++) {
            float b0 = Bs[col0 + nt * 8 + tig * 2];
            float b1 = Bs[col0 + nt * 8 + tig * 2 + 1];
#pragma unroll
            for (int mt = 0; mt < 2; mt++) {
                c[mt][nt][0] = b0; c[mt][nt][1] = b1;
                c[mt][nt][2] = b0; c[mt][nt][3] = b1;
            }
        }

#pragma unroll
        for (int s = 0; s < 3; s++) {
            const uint32_t* Aa = (s < 2) ? AH : AL;
            const uint32_t* Ba = (s == 1) ? BL : BH;
#pragma unroll
            for (int ks = 0; ks < 4; ks++) {
                int ab = (mo + g) * 36 + ks * 8 + tig;
                uint32_t a[2][4];
                a[0][0] = Aa[ab];        a[0][2] = Aa[ab + 4];
                a[0][1] = Aa[ab + 288];  a[0][3] = Aa[ab + 292];
                a[1][0] = Aa[ab + 576];  a[1][2] = Aa[ab + 580];
                a[1][1] = Aa[ab + 864];  a[1][3] = Aa[ab + 868];
                int bb = g * 36 + ks * 8 + tig;
                uint32_t b[8][2];
#pragma unroll
                for (int nt = 0; nt < 8; nt++) {
                    b[nt][0] = Ba[bb + nt * 288];
                    b[nt][1] = Ba[bb + nt * 288 + 4];
                }
#pragma unroll
                for (int mt = 0; mt < 2; mt++)
#pragma unroll
                    for (int nt = 0; nt < 8; nt++)
                        mma16816(c[mt][nt], a[mt], b[nt]);
            }
        }

#pragma unroll
        for (int mt = 0; mt < 2; mt++) {
            size_t ra = row0 + mo + mt * 16 + g;
#pragma unroll
            for (int nt = 0; nt < 8; nt++) {
                float* p = Out + ra * OC + col0 + nt * 8 + tig * 2;
                *(float2*)p = make_float2(c[mt][nt][0], c[mt][nt][1]);
                *(float2*)(p + 8 * (size_t)OC) = make_float2(c[mt][nt][2], c[mt][nt][3]);
            }
        }
    }
}

// ---------------- blocked output projection + gelu + skip (FFMA2) ----------
__global__ void __launch_bounds__(128) k_out2(int typ, const float* __restrict__ Wa,
                                              const float* __restrict__ ba,
                                              const float* __restrict__ skip, int l) {
    extern __shared__ float smf[];
    const float* agg = typ ? gAggB : gAggA;
    float* X = typ ? gXB : gXA;
    const float* w = Wa + (size_t)(l * 2 + typ) * 4096;

    float* Xs = smf;
    float* Ws = smf + 64 * XST;
    float* Bs = smf + 64 * XST + 64 * WST;

    int tid = threadIdx.x;
    size_t row0 = (size_t)blockIdx.x * 128;

    for (int i = tid; i < 4096; i += 128) {
        int k = i >> 6, col = i & 63;
        Ws[k * WST + col + ((col >> 5) << 2)] = w[k * 64 + col];
    }
    if (tid < 64) Bs[tid] = ba[(l * 2 + typ) * 64 + tid];

    const float4* A4 = (const float4*)(agg + row0 * 64);
#pragma unroll
    for (int i = 0; i < 16; i++) {
        int idx = i * 128 + tid;
        int row = idx >> 4, kq = idx & 15;
        float4 v = A4[idx];
        Xs[(4 * kq + 0) * XST + row] = gelu_f(v.x);
        Xs[(4 * kq + 1) * XST + row] = gelu_f(v.y);
        Xs[(4 * kq + 2) * XST + row] = gelu_f(v.z);
        Xs[(4 * kq + 3) * XST + row] = gelu_f(v.w);
    }
    __syncthreads();

    int tc = tid & 7, tr = tid >> 3;
    int cb = tc * 8 + ((tc >> 2) << 2);
    int rb = tr * 8;

    u64 acc[8][4];
#pragma unroll
    for (int cp = 0; cp < 4; cp++) {
        u64 b = packf2(Bs[tc * 8 + 2 * cp], Bs[tc * 8 + 2 * cp + 1]);
#pragma unroll
        for (int r = 0; r < 8; r++) acc[r][cp] = b;
    }

#pragma unroll 4
    for (int k = 0; k < 64; k++) {
        float4 xa = *(const float4*)(Xs + k * XST + rb);
        float4 xb = *(const float4*)(Xs + k * XST + rb + 4);
        ulonglong2 wA = *(const ulonglong2*)(Ws + k * WST + cb);
        ulonglong2 wB = *(const ulonglong2*)(Ws + k * WST + cb + 4);
        float xr[8] = {xa.x, xa.y, xa.z, xa.w, xb.x, xb.y, xb.z, xb.w};
#pragma unroll
        for (int r = 0; r < 8; r++) {
            u64 xx = packf2(xr[r], xr[r]);
            fma2(acc[r][0], wA.x, xx);
            fma2(acc[r][1], wA.y, xx);
            fma2(acc[r][2], wB.x, xx);
            fma2(acc[r][3], wB.y, xx);
        }
    }

    float sg = 1.0f / (1.0f + __expf(-skip[l * 2 + typ]));
    float omg = 1.0f - sg;
    u64 sgp = packf2(sg, sg), omgp = packf2(omg, omg);

#pragma unroll
    for (int r = 0; r < 8; r++) {
        float* xp = X + (row0 + rb + r) * 64 + tc * 8;
        ulonglong2 xo = *(ulonglong2*)xp;
        ulonglong2 xo2 = *(ulonglong2*)(xp + 4);
        u64 y0 = mul2(xo.x,  omgp); fma2(y0, acc[r][0], sgp);
        u64 y1 = mul2(xo.y,  omgp); fma2(y1, acc[r][1], sgp);
        u64 y2 = mul2(xo2.x, omgp); fma2(y2, acc[r][2], sgp);
        u64 y3 = mul2(xo2.y, omgp); fma2(y3, acc[r][3], sgp);
        ulonglong2 s0; s0.x = y0; s0.y = y1;
        ulonglong2 s1; s1.x = y2; s1.y = y3;
        *(ulonglong2*)xp = s0;
        *(ulonglong2*)(xp + 4) = s1;
    }
}

// ---------------- edge attention: TWO-STREAM online softmax ----------------
template <int REL, int ACCUM>
__global__ void k_edge(const float* __restrict__ p_rel, int l) {
    int t = blockIdx.x * blockDim.x + threadIdx.x;
    int gw = t >> 5, lane = t & 31;
    if (gw >= NN) return;

    const float* Q;   int qs;
    const float* Src; int ss, off;
    float* Agg;
    if (REL == 0) { Q = gBufB; qs = 192; Src = gBufA; ss = 320; off = 64;  Agg = gAggB; }
    else if (REL == 1) { Q = gBufA; qs = 320; Src = gBufB; ss = 192; off = 64;  Agg = gAggA; }
    else { Q = gBufA; qs = 320; Src = gBufA; ss = 320; off = 192; Agg = gAggA; }

    float scl = p_rel[l * 3 + REL] * 0.125f;
    float2 q = *(const float2*)(Q + (size_t)gw * qs + 2 * lane);

    const int* __restrict__ rowptr = gRowptr[REL];
    const int* __restrict__ csr = gCsr[REL];
    int beg = rowptr[gw], end = rowptr[gw + 1];

    float mxA = -3.0e38f, denA = 0.f, s0A = 0.f, s1A = 0.f;
    float mxB = -3.0e38f, denB = 0.f, s0B = 0.f, s1B = 0.f;

    int j = beg;
    for (; j + 2 <= end; j += 2) {
        int sA = __ldg(&csr[j]);
        int sB = __ldg(&csr[j + 1]);
        float4 kvA = *(const float4*)(Src + (size_t)sA * ss + off + 4 * lane);
        float4 kvB = *(const float4*)(Src + (size_t)sB * ss + off + 4 * lane);
        float pA = fmaf(q.x, kvA.x, q.y * kvA.y);
        float pB = fmaf(q.x, kvB.x, q.y * kvB.y);
        warpsum2(pA, pB);
        online_upd(pA * scl, kvA.z, kvA.w, mxA, denA, s0A, s1A);
        online_upd(pB * scl, kvB.z, kvB.w, mxB, denB, s0B, s1B);
    }
    if (j < end) {
        int s = __ldg(&csr[j]);
        float4 kv = *(const float4*)(Src + (size_t)s * ss + off + 4 * lane);
        float sc = warpsum(fmaf(q.x, kv.x, q.y * kv.y)) * scl;
        online_upd(sc, kv.z, kv.w, mxA, denA, s0A, s1A);
    }

    float a0 = 0.f, a1 = 0.f;
    {
        float m = fmaxf(mxA, mxB);
        float fA = __expf(mxA - m), fB = __expf(mxB - m);
        float den = denA * fA + denB * fB;
        float s0 = s0A * fA + s0B * fB;
        float s1 = s1A * fA + s1B * fB;
        if (den > 0.f) {
            float inv = 1.0f / den;
            a0 = s0 * inv;
            a1 = s1 * inv;
        }
    }
    float2* ap = (float2*)(Agg + (size_t)gw * 64 + 2 * lane);
    if (ACCUM) {
        float2 old = *ap;
        *ap = make_float2(old.x + a0, old.y + a1);
    } else {
        *ap = make_float2(a0, a1);
    }
}

// ---------------- final pool + linear ----------------
__global__ void k_zero_out(float* out) { out[0] = 0.f; }

__global__ void k_final(const float* __restrict__ lw, const float* __restrict__ lb,
                        float* out) {
    float acc = 0.f;
    const int total = 2 * NN * 64;
    for (int i = blockIdx.x * blockDim.x + threadIdx.x; i < total;
         i += gridDim.x * blockDim.x) {
        float v = (i < NN * 64) ? gXA[i] : gXB[i - NN * 64];
        acc += v * lw[i & 63];
    }
    __shared__ float red[256];
    red[threadIdx.x] = acc;
    __syncthreads();
    for (int s = 128; s; s >>= 1) {
        if (threadIdx.x < s) red[threadIdx.x] += red[threadIdx.x + s];
        __syncthreads();
    }
    if (threadIdx.x == 0) {
        float v = red[0];
        if (blockIdx.x == 0) v += lb[0];
        atomicAdd(out, v);
    }
}

// ---------------- launch ----------------
extern "C" void kernel_launch(void* const* d_in, const int* in_sizes, int n_in,
                              void* d_out, int out_size) {
    const float* xA   = (const float*)d_in[0];
    const float* xB   = (const float*)d_in[1];
    const float* Wk   = (const float*)d_in[2];
    const float* bk   = (const float*)d_in[3];
    const float* Wq   = (const float*)d_in[4];
    const float* bq   = (const float*)d_in[5];
    const float* Wv   = (const float*)d_in[6];
    const float* bv   = (const float*)d_in[7];
    const float* Ar   = (const float*)d_in[8];
    const float* Mr   = (const float*)d_in[9];
    const float* pr   = (const float*)d_in[10];
    const float* Wa   = (const float*)d_in[11];
    const float* ba   = (const float*)d_in[12];
    const float* skip = (const float*)d_in[13];
    const float* lw   = (const float*)d_in[14];
    const float* lb   = (const float*)d_in[15];
    const int* e0 = (const int*)d_in[16];
    const int* e1 = (const int*)d_in[17];
    const int* e2 = (const int*)d_in[18];

    // one-time stream/event setup (host-side only; no device allocations)
    static cudaStream_t sAux = nullptr;
    static cudaEvent_t evFork, evCsr, evP[3], evA[3];
    if (!sAux) {
        cudaStreamCreateWithFlags(&sAux, cudaStreamNonBlocking);
        cudaEventCreateWithFlags(&evFork, cudaEventDisableTiming);
        cudaEventCreateWithFlags(&evCsr, cudaEventDisableTiming);
        for (int i = 0; i < 3; i++) {
            cudaEventCreateWithFlags(&evP[i], cudaEventDisableTiming);
            cudaEventCreateWithFlags(&evA[i], cudaEventDisableTiming);
        }
        cudaFuncSetAttribute(k_proj_mma, cudaFuncAttributeMaxDynamicSharedMemorySize, SMEM_MMA2);
        cudaFuncSetAttribute(k_out2, cudaFuncAttributeMaxDynamicSharedMemorySize, SMEM_BYTES);
        cudaFuncSetAttribute(k_proj_mma, cudaFuncAttributePreferredSharedMemoryCarveout, 100);
        cudaFuncSetAttribute(k_out2, cudaFuncAttributePreferredSharedMemoryCarveout, 100);
    }

    // fork aux stream; CSR build runs concurrently with layer-0 GEMMs
    cudaEventRecord(evFork, MAIN_STREAM);
    cudaStreamWaitEvent(sAux, evFork, 0);
    k_zero_deg<<<dim3(NN / 256, 3), 256, 0, sAux>>>();
    k_hist<<<dim3((EE + 255) / 256, 3), 256, 0, sAux>>>(e0, e1, e2);
    k_blocksum<<<dim3(128, 3), 1024, 0, sAux>>>();
    k_scanblk<<<1, 128, 0, sAux>>>();
    k_scanlocal<<<dim3(128, 3), 1024, 0, sAux>>>();
    k_scatter<<<dim3((EE + 255) / 256, 3), 256, 0, sAux>>>(e0, e1, e2);
    cudaEventRecord(evCsr, sAux);

    // main stream: layer-0 GEMMs
    k_copyin<<<NN * 64 / 256, 256>>>(xA, xB);
    k_fuse<<<130, 256>>>(Wk, bk, Wq, bq, Wv, bv, Ar, Mr, 0);
    k_packW<<<64, 256>>>();
    k_proj_mma<<<512, 256, SMEM_MMA2>>>(0);
    k_proj_mma<<<512, 256, SMEM_MMA2>>>(1);
    cudaStreamWaitEvent(MAIN_STREAM, evCsr, 0);

    for (int l = 0; l < 3; l++) {
        // proj for this layer complete on main; fork the rel1/rel2/out(A) track
        cudaEventRecord(evP[l], MAIN_STREAM);
        cudaStreamWaitEvent(sAux, evP[l], 0);
        k_edge<1, 0><<<16384, 256, 0, sAux>>>(pr, l);   // B -> A, writes gAggA
        k_edge<2, 1><<<16384, 256, 0, sAux>>>(pr, l);   // A -> A, accumulates gAggA
        k_out2<<<1024, 128, SMEM_BYTES, sAux>>>(0, Wa, ba, skip, l);
        cudaEventRecord(evA[l], sAux);

        // main track: rel0 and out(B)
        k_edge<0, 0><<<16384, 256>>>(pr, l);            // A -> B, writes gAggB
        k_out2<<<1024, 128, SMEM_BYTES>>>(1, Wa, ba, skip, l);

        if (l < 2) {
            k_fuse<<<130, 256>>>(Wk, bk, Wq, bq, Wv, bv, Ar, Mr, l + 1);
            k_packW<<<64, 256>>>();
            cudaStreamWaitEvent(MAIN_STREAM, evA[l], 0);  // gXA ready; bufA/bufB free
            k_proj_mma<<<512, 256, SMEM_MMA2>>>(0);
            k_proj_mma<<<512, 256, SMEM_MMA2>>>(1);
        }
    }

    cudaStreamWaitEvent(MAIN_STREAM, evA[2], 0);   // join aux before readout
    k_zero_out<<<1, 1>>>((float*)d_out);
    k_final<<<1024, 256>>>(lw, lb, (float*)d_out);
}